// round 9
// baseline (speedup 1.0000x reference)
#include <cuda_runtime.h>

// RotationPerturbationLayer as zero-padded bilinear rotation resample.
// theta: [B=4] deg, image: [C=3, H=80, W=80] fp32 -> out [B, C, H, W].
//
// R6 = R4 resubmit (R5 was an infra failure, kernel never ran):
// 2 pixels/thread along x (shared sincos + incremental source coords),
// float2 stores, per-axis masked weights. 80 blocks x 160 threads = 12800
// threads covering 25600 pixels; single wave on 80 SMs.

#define H 80
#define W 80
#define C 3
#define B 4
#define NPIX (H * W)

__device__ __forceinline__ void sample_px(const float* __restrict__ c0,
                                          const float* __restrict__ c1,
                                          const float* __restrict__ c2,
                                          float src_x, float src_y,
                                          float& r0, float& r1, float& r2) {
    float fx0 = floorf(src_x);
    float fy0 = floorf(src_y);
    int x0 = (int)fx0;
    int y0 = (int)fy0;
    int x1 = x0 + 1;
    int y1 = y0 + 1;
    float ax = src_x - fx0;
    float ay = src_y - fy0;

    // per-axis masked tent weights (zero-padding: product is 0 if either axis OOB)
    float wx0 = ((x0 >= 0) & (x0 < W)) ? (1.0f - ax) : 0.0f;
    float wx1 = ((x1 >= 0) & (x1 < W)) ? ax          : 0.0f;
    float wy0 = ((y0 >= 0) & (y0 < H)) ? (1.0f - ay) : 0.0f;
    float wy1 = ((y1 >= 0) & (y1 < H)) ? ay          : 0.0f;

    float m00 = wy0 * wx0;
    float m10 = wy0 * wx1;
    float m01 = wy1 * wx0;
    float m11 = wy1 * wx1;

    int xc0 = min(max(x0, 0), W - 1);
    int xc1 = min(max(x1, 0), W - 1);
    int yc0 = min(max(y0, 0), H - 1);
    int yc1 = min(max(y1, 0), H - 1);

    int i00 = yc0 * W + xc0;
    int i10 = yc0 * W + xc1;
    int i01 = yc1 * W + xc0;
    int i11 = yc1 * W + xc1;

    // 12 independent gathers, batched (MLP high, one exposed L2 latency)
    float v00_0 = __ldg(c0 + i00);
    float v10_0 = __ldg(c0 + i10);
    float v01_0 = __ldg(c0 + i01);
    float v11_0 = __ldg(c0 + i11);
    float v00_1 = __ldg(c1 + i00);
    float v10_1 = __ldg(c1 + i10);
    float v01_1 = __ldg(c1 + i01);
    float v11_1 = __ldg(c1 + i11);
    float v00_2 = __ldg(c2 + i00);
    float v10_2 = __ldg(c2 + i10);
    float v01_2 = __ldg(c2 + i01);
    float v11_2 = __ldg(c2 + i11);

    r0 = m00 * v00_0;
    r0 = fmaf(m10, v10_0, r0);
    r0 = fmaf(m01, v01_0, r0);
    r0 = fmaf(m11, v11_0, r0);

    r1 = m00 * v00_1;
    r1 = fmaf(m10, v10_1, r1);
    r1 = fmaf(m01, v01_1, r1);
    r1 = fmaf(m11, v11_1, r1);

    r2 = m00 * v00_2;
    r2 = fmaf(m10, v10_2, r2);
    r2 = fmaf(m01, v01_2, r2);
    r2 = fmaf(m11, v11_2, r2);
}

__global__ __launch_bounds__(160)
void rot_bilinear_kernel(const float* __restrict__ theta,
                         const float* __restrict__ image,
                         float* __restrict__ out) {
    const int x  = threadIdx.x * 2;                  // 0,2,..,78
    const int y  = blockIdx.x * 4 + threadIdx.y;     // 0..79
    const int b  = blockIdx.y;                       // 0..3

    const float cx = (W - 1) * 0.5f;
    const float cy = (H - 1) * 0.5f;

    float th = theta[b] * 0.017453292519943295f;
    float s, c;
    __sincosf(th, &s, &c);

    float x_rel = (float)x - cx;
    float y_rel = (float)y - cy;

    // pixel 0 source coords; pixel 1 is one step along +x: (+c, -s)
    float src_x0 = fmaf(c,  x_rel, fmaf(s, y_rel, cx));
    float src_y0 = fmaf(-s, x_rel, fmaf(c, y_rel, cy));
    float src_x1 = src_x0 + c;
    float src_y1 = src_y0 - s;

    const float* c0 = image;
    const float* c1 = image + NPIX;
    const float* c2 = image + 2 * NPIX;

    float a0, a1, a2, b0, b1, b2;
    sample_px(c0, c1, c2, src_x0, src_y0, a0, a1, a2);
    sample_px(c0, c1, c2, src_x1, src_y1, b0, b1, b2);

    int pix = y * W + x;                             // even -> 8B aligned
    float* ob = out + (size_t)b * C * NPIX + pix;

    reinterpret_cast<float2*>(ob + 0 * NPIX)[0] = make_float2(a0, b0);
    reinterpret_cast<float2*>(ob + 1 * NPIX)[0] = make_float2(a1, b1);
    reinterpret_cast<float2*>(ob + 2 * NPIX)[0] = make_float2(a2, b2);
}

extern "C" void kernel_launch(void* const* d_in, const int* in_sizes, int n_in,
                              void* d_out, int out_size) {
    const float* theta = (const float*)d_in[0];
    const float* image = (const float*)d_in[1];
    if (n_in >= 2 && in_sizes[0] != 4 && in_sizes[1] == 4) {
        theta = (const float*)d_in[1];
        image = (const float*)d_in[0];
    }
    float* out = (float*)d_out;

    dim3 block(40, 4, 1);        // 160 threads, 2 px each along x
    dim3 grid(H / 4, B, 1);      // 20 x 4 = 80 blocks, one wave
    rot_bilinear_kernel<<<grid, block>>>(theta, image, out);
}